// round 1
// baseline (speedup 1.0000x reference)
#include <cuda_runtime.h>

// Problem constants (B=32, L=1024, D=64)
#define BB 32
#define LL 1024
#define DD 64

// ---------------------------------------------------------------------------
// The reference collapses algebraically:
//   - The causal triu(k=0) mask (includes diagonal) adds -2^32+1, which in
//     fp32 makes every diagonal softmax entry exactly 0 for rows m>=1
//     (exp underflow vs finite unmasked max) and exactly 1/L for row m=0
//     (all entries identical after fp32 rounding -> uniform softmax).
//   - output[b,l,d] = diag(score)[b,l] * sum_m x[b,m,d]
//     => output[:,0,:]  = sum_l x[b,l,:] / 1024,  output[:,1:,:] = 0.
// W1,b1,W2,b2,timestamp do not influence the output at all.
// ---------------------------------------------------------------------------

__global__ void um_zero_kernel(float4* __restrict__ out, int n4) {
    int i = blockIdx.x * blockDim.x + threadIdx.x;
    if (i < n4) out[i] = make_float4(0.f, 0.f, 0.f, 0.f);
}

// grid (B, 8): each block reduces a 128-row chunk of x[b] over L, coalesced in d.
__global__ void um_rowsum_kernel(const float* __restrict__ x,
                                 float* __restrict__ out) {
    const int b   = blockIdx.x;
    const int c   = blockIdx.y;          // chunk of 128 rows
    const int tid = threadIdx.x;         // 256 threads
    const int d   = tid & 63;            // 0..63  (contiguous -> coalesced)
    const int lg  = tid >> 6;            // 0..3

    const float* base = x + ((size_t)b * LL + (size_t)c * 128) * DD;

    float s = 0.f;
    #pragma unroll
    for (int j = 0; j < 32; ++j) {
        s += base[(size_t)(lg + 4 * j) * DD + d];
    }

    __shared__ float sm[256];
    sm[tid] = s;
    __syncthreads();

    if (lg == 0) {
        float t = sm[d] + sm[64 + d] + sm[128 + d] + sm[192 + d];
        // out row 0 of batch b; zeroed by um_zero_kernel earlier in the stream
        atomicAdd(&out[(size_t)b * LL * DD + d], t * (1.0f / 1024.0f));
    }
}

extern "C" void kernel_launch(void* const* d_in, const int* in_sizes, int n_in,
                              void* d_out, int out_size) {
    const float* x = (const float*)d_in[0];   // user_embedding [B, L, D]
    float* out = (float*)d_out;               // [B, L, D]

    // 1) zero the whole output (it is poisoned to 0xAA)
    int n4 = out_size >> 2;                   // out_size = 2,097,152 floats
    int threads = 512;
    int blocks = (n4 + threads - 1) / threads;
    um_zero_kernel<<<blocks, threads>>>((float4*)out, n4);

    // 2) reduce x over L into out[:, 0, :] (scaled by 1/1024)
    dim3 grid(BB, 8);
    um_rowsum_kernel<<<grid, 256>>>(x, out);
}

// round 2
// speedup vs baseline: 1.0037x; 1.0037x over previous
#include <cuda_runtime.h>

// Problem constants (B=32, L=1024, D=64)
//
// Algebraic collapse of the reference (see R1 analysis):
//   triu(k=0) mask with -2^32+1 makes diag(softmax) == 0 for rows m>=1
//   (exp underflow) and == 1/L for row m=0 (uniform row after fp32 rounding).
//   => out[b,0,:] = sum_l x[b,l,:] / 1024 ;  out[b,1:,:] = 0.
//   W1,b1,W2,b2,timestamp are dead inputs.
//
// Single fused kernel:
//   blocks [0,128):   reduction. block = (b, quarter q of D). Each owns 16
//                     float4-columns' worth? no -- owns 4 float4 columns
//                     (16 floats) of batch b, sums all 1024 rows, writes
//                     out[b,0, q*16 : q*16+16] directly (exclusive owner).
//   blocks [128,512): zeroing. grid-stride over out as float4, skipping the
//                     first 16 float4 (= row 0) of each batch -- disjoint
//                     from the reduction writes, so no ordering needed.

#define RED_BLOCKS   128
#define ZERO_BLOCKS  384
#define TOTAL_BLOCKS (RED_BLOCKS + ZERO_BLOCKS)

// per batch: 1024 rows * 16 float4/row = 16384 float4
#define F4_PER_BATCH 16384u
#define F4_PER_ROW   16u
#define N_F4_TOTAL   (32u * F4_PER_BATCH)

__global__ void __launch_bounds__(256) um_fused_kernel(
    const float4* __restrict__ x4, float4* __restrict__ out4)
{
    const int bid = blockIdx.x;
    const int tid = threadIdx.x;

    if (bid < RED_BLOCKS) {
        // ---- reduction: batch b, quarter q (float4 columns q*4 .. q*4+3) ----
        const int b  = bid >> 2;
        const int q  = bid & 3;
        const int c  = tid & 3;        // float4-column within quarter
        const int lg = tid >> 2;       // row group 0..63

        const float4* base = x4 + (size_t)b * F4_PER_BATCH + q * 4 + c;

        float4 s = make_float4(0.f, 0.f, 0.f, 0.f);
        #pragma unroll
        for (int j = 0; j < 16; ++j) {
            float4 v = base[(size_t)(lg + 64 * j) * F4_PER_ROW];
            s.x += v.x; s.y += v.y; s.z += v.z; s.w += v.w;
        }

        __shared__ float4 sm[256];
        sm[tid] = s;
        __syncthreads();

        // tree reduce; strides are multiples of 4 so float4-column lanes
        // (tid & 3) never mix.
        #pragma unroll
        for (int st = 128; st >= 4; st >>= 1) {
            if (tid < st) {
                float4 a = sm[tid], bb = sm[tid + st];
                a.x += bb.x; a.y += bb.y; a.z += bb.z; a.w += bb.w;
                sm[tid] = a;
            }
            __syncthreads();
        }

        if (tid < 4) {
            float4 a = sm[tid];
            const float inv = 1.0f / 1024.0f;
            a.x *= inv; a.y *= inv; a.z *= inv; a.w *= inv;
            out4[(size_t)b * F4_PER_BATCH + q * 4 + tid] = a;
        }
    } else {
        // ---- zeroing: all of out except row 0 of each batch ----
        const unsigned zid  = (unsigned)(bid - RED_BLOCKS);
        const unsigned step = ZERO_BLOCKS * 256u;
        const float4 z = make_float4(0.f, 0.f, 0.f, 0.f);
        for (unsigned i = zid * 256u + (unsigned)tid; i < N_F4_TOTAL; i += step) {
            if ((i & (F4_PER_BATCH - 1u)) >= F4_PER_ROW)  // skip row 0
                out4[i] = z;
        }
    }
}

extern "C" void kernel_launch(void* const* d_in, const int* in_sizes, int n_in,
                              void* d_out, int out_size) {
    const float4* x4 = (const float4*)d_in[0];   // user_embedding [32,1024,64]
    float4* out4 = (float4*)d_out;               // [32,1024,64]
    um_fused_kernel<<<TOTAL_BLOCKS, 256>>>(x4, out4);
}